// round 1
// baseline (speedup 1.0000x reference)
#include <cuda_runtime.h>

// ---------------- problem constants ----------------
#define NB    384          // proposals per image
#define NC    11           // classes incl background
#define NFG   10           // foreground classes
#define NIMG  2            // images
#define NGRP  (NIMG*NFG)   // 20 NMS groups
#define MTOT  (NIMG*NB)    // 768 proposals
#define DET   100
#define MASKW 12           // ceil(384/32)
#define EPSF  1e-8f
#define SCORE_TH 0.05f
#define NMS_TH   0.5f
#define XFORM_CLIP 4.135166556742356f   // log(1000/16)
#define SUBB  37           // pair-kernel blocks per group

// ---------------- device scratch (no allocs allowed) ----------------
__device__ float    g_scores[NGRP*NB];
__device__ float    g_boxes [NGRP*NB*5];
__device__ float    g_corn  [NGRP*NB*8];
__device__ float    g_area  [NGRP*NB];
__device__ float    g_rad   [NGRP*NB];
__device__ int      g_vcnt  [NGRP];
__device__ int      g_vlist [NGRP*NB];
__device__ unsigned g_mask  [NGRP*NB*MASKW];
__device__ float    g_kept  [NGRP*NB];

// ---------------- kernel 1: softmax + decode + corners ----------------
__global__ void k_decode(const float* __restrict__ logits,
                         const float* __restrict__ reg,
                         const float* __restrict__ rr)
{
    int m = blockIdx.x*blockDim.x + threadIdx.x;
    if (m >= MTOT) return;

    float l[NC];
    float mx = -1e30f;
    #pragma unroll
    for (int c=0;c<NC;c++){ l[c] = logits[m*NC+c]; mx = fmaxf(mx, l[c]); }
    float s = 0.f;
    #pragma unroll
    for (int c=0;c<NC;c++){ l[c] = expf(l[c]-mx); s += l[c]; }

    float xc = rr[m*5+0], yc = rr[m*5+1];
    float w  = rr[m*5+2], h  = rr[m*5+3], a = rr[m*5+4];
    int b = m / NB, n = m % NB;

    #pragma unroll 1
    for (int c=1;c<NC;c++){
        const float* r = &reg[m*(NC*5) + c*5];
        float dx = r[0]/10.0f;
        float dy = r[1]/10.0f;
        float dw = fminf(r[2]/5.0f, XFORM_CLIP);
        float dh = fminf(r[3]/5.0f, XFORM_CLIP);
        float da = r[4]/1.0f;

        float px = dx*w + xc;
        float py = dy*h + yc;
        float pw = expf(dw)*w;
        float ph = expf(dh)*h;
        float pa = da*(float)(180.0/3.14159265358979323846) + a;
        // jnp-style mod: sign of divisor
        float x2 = pa + 180.0f;
        float rm = fmodf(x2, 360.0f);
        if (rm < 0.0f) rm += 360.0f;
        pa = rm - 180.0f;

        int g = b*NFG + (c-1);
        int o = g*NB + n;
        g_scores[o]    = l[c]/s;
        g_boxes[o*5+0] = px; g_boxes[o*5+1] = py;
        g_boxes[o*5+2] = pw; g_boxes[o*5+3] = ph; g_boxes[o*5+4] = pa;
        g_area[o]      = pw*ph;
        g_rad[o]       = 0.5f*sqrtf(pw*pw + ph*ph);

        float t  = pa*(float)(3.14159265358979323846/180.0);
        float cs = cosf(t), sn = sinf(t);
        float hx = pw*0.5f, hy = ph*0.5f;
        float lx[4] = {-hx, hx, hx, -hx};
        float ly[4] = {-hy, -hy, hy, hy};
        #pragma unroll
        for (int k=0;k<4;k++){
            g_corn[o*8+2*k]   = px + lx[k]*cs - ly[k]*sn;
            g_corn[o*8+2*k+1] = py + lx[k]*sn + ly[k]*cs;
        }
    }
}

// ---------------- kernel 2: per-group sort (score desc, idx asc) ----------------
__global__ void k_sort()
{
    int g = blockIdx.x;
    int t = threadIdx.x;                 // 512 threads
    __shared__ unsigned long long sk[512];

    bool val = false;
    if (t < NB){
        float sc = g_scores[g*NB+t];
        val = sc > SCORE_TH;
        float kf = val ? sc : __int_as_float(0xFF800000);   // -inf for invalid
        unsigned ub = __float_as_uint(kf);
        ub = (ub & 0x80000000u) ? ~ub : (ub | 0x80000000u); // ascending-sortable
        sk[t] = (((unsigned long long)(~ub)) << 32) | (unsigned)t; // desc score, asc idx
        g_kept[g*NB+t] = -1.0f;
    } else {
        sk[t] = 0xFFFFFFFFFFFFFFFFull;
    }
    // zero this group's suppression mask every launch (graph replays!)
    for (int w = t; w < NB*MASKW; w += 512) g_mask[g*NB*MASKW + w] = 0u;

    int v = __syncthreads_count(val);    // also a full barrier
    if (t == 0) g_vcnt[g] = v;

    for (int k=2;k<=512;k<<=1)
        for (int j=k>>1;j>0;j>>=1){
            int ixj = t ^ j;
            if (ixj > t){
                unsigned long long A = sk[t], Bv = sk[ixj];
                if ((A > Bv) == ((t & k) == 0)){ sk[t] = Bv; sk[ixj] = A; }
            }
            __syncthreads();
        }

    if (t < v) g_vlist[g*NB+t] = (int)(sk[t] & 0xFFFFFFFFull);
}

// ---------------- rotated-rect intersection (mirrors reference) ----------------
__device__ __forceinline__ float crs(float ax,float ay,float bx,float by){
    return ax*by - ay*bx;
}

__device__ float inter_area_dev(const float* __restrict__ CA, const float* __restrict__ CB)
{
    float ax[4],ay[4],bx4[4],by4[4];
    #pragma unroll
    for (int k=0;k<4;k++){ ax[k]=CA[2*k]; ay[k]=CA[2*k+1]; bx4[k]=CB[2*k]; by4[k]=CB[2*k+1]; }
    float d1x[4],d1y[4],d2x[4],d2y[4];
    #pragma unroll
    for (int k=0;k<4;k++){
        d1x[k]=ax[(k+1)&3]-ax[k];  d1y[k]=ay[(k+1)&3]-ay[k];
        d2x[k]=bx4[(k+1)&3]-bx4[k]; d2y[k]=by4[(k+1)&3]-by4[k];
    }

    float px[24], py[24]; bool ok[24];
    #pragma unroll
    for (int i=0;i<4;i++){
        #pragma unroll
        for (int j=0;j<4;j++){
            float den  = crs(d1x[i],d1y[i],d2x[j],d2y[j]);
            float dfx  = bx4[j]-ax[i], dfy = by4[j]-ay[i];
            float dens = (fabsf(den) < EPSF) ? 1.0f : den;
            float t = crs(dfx,dfy,d2x[j],d2y[j]) / dens;
            float u = crs(dfx,dfy,d1x[i],d1y[i]) / dens;
            bool o = (fabsf(den) >= EPSF) && (t>=0.0f) && (t<=1.0f) && (u>=0.0f) && (u<=1.0f);
            px[4*i+j] = ax[i] + t*d1x[i];
            py[4*i+j] = ay[i] + t*d1y[i];
            ok[4*i+j] = o;
        }
    }
    // A corners inside B
    #pragma unroll
    for (int p=0;p<4;p++){
        bool allpos=true, allneg=true;
        #pragma unroll
        for (int e=0;e<4;e++){
            float cr = crs(d2x[e],d2y[e], ax[p]-bx4[e], ay[p]-by4[e]);
            allpos = allpos && (cr >= -1e-6f);
            allneg = allneg && (cr <=  1e-6f);
        }
        ok[16+p] = allpos || allneg;
        px[16+p] = ax[p]; py[16+p] = ay[p];
    }
    // B corners inside A
    #pragma unroll
    for (int p=0;p<4;p++){
        bool allpos=true, allneg=true;
        #pragma unroll
        for (int e=0;e<4;e++){
            float cr = crs(d1x[e],d1y[e], bx4[p]-ax[e], by4[p]-ay[e]);
            allpos = allpos && (cr >= -1e-6f);
            allneg = allneg && (cr <=  1e-6f);
        }
        ok[20+p] = allpos || allneg;
        px[20+p] = bx4[p]; py[20+p] = by4[p];
    }

    int nv = 0; float cx = 0.0f, cy = 0.0f;
    #pragma unroll
    for (int i=0;i<24;i++) if (ok[i]){ nv++; cx += px[i]; cy += py[i]; }
    if (nv < 3) return 0.0f;
    cx /= (float)nv;  cy /= (float)nv;

    // Valid points + ONE centroid vertex at angle +0.0 (all parked points
    // in the reference collapse to this single insertion: cross(c,c)=0).
    float sxp[25], syp[25], sap[25];
    int cnt = 0;
    #pragma unroll
    for (int i=0;i<24;i++) if (ok[i]){
        sxp[cnt]=px[i]; syp[cnt]=py[i];
        sap[cnt]=atan2f(py[i]-cy, px[i]-cx);
        cnt++;
    }
    sxp[cnt]=cx; syp[cnt]=cy; sap[cnt]=0.0f; cnt++;

    // stable insertion sort by angle
    for (int k=1;k<cnt;k++){
        float a0=sap[k], x0=sxp[k], y0=syp[k];
        int mo=k-1;
        while (mo>=0 && sap[mo] > a0){
            sap[mo+1]=sap[mo]; sxp[mo+1]=sxp[mo]; syp[mo+1]=syp[mo]; mo--;
        }
        sap[mo+1]=a0; sxp[mo+1]=x0; syp[mo+1]=y0;
    }
    float s = 0.0f;
    for (int i=0;i<cnt;i++){
        int j = (i+1<cnt) ? i+1 : 0;
        s += sxp[i]*syp[j] - syp[i]*sxp[j];
    }
    return 0.5f*fabsf(s);
}

__device__ bool iou_suppress(int ba, int bb)
{
    float aA = g_area[ba], aB = g_area[bb];
    float mn = fminf(aA,aB), sm = aA + aB;
    // IoU>0.5 requires inter > (aA+aB)/3 and inter <= min(aA,aB) (exact bound + fp margin)
    if (3.0f*mn <= sm*(1.0f - 1e-4f)) return false;
    float dx = g_boxes[ba*5]   - g_boxes[bb*5];
    float dy = g_boxes[ba*5+1] - g_boxes[bb*5+1];
    float rr = g_rad[ba] + g_rad[bb];
    if (dx*dx + dy*dy >= rr*rr) return false;        // disjoint -> inter=0 -> IoU<=0.5
    float inter = inter_area_dev(&g_corn[ba*8], &g_corn[bb*8]);
    float iou = inter / (aA + aB - inter + EPSF);
    return iou > NMS_TH;
}

// ---------------- kernel 3: all valid pairs -> suppression bitmask ----------------
__global__ void k_pairs()
{
    int g   = blockIdx.x / SUBB;
    int sub = blockIdx.x % SUBB;
    int v = g_vcnt[g];
    int P = v*(v-1)/2;
    for (int p = sub*blockDim.x + threadIdx.x; p < P; p += SUBB*blockDim.x){
        // decode p -> (i<j): p = j*(j-1)/2 + i
        int j = (int)((1.0f + sqrtf(1.0f + 8.0f*(float)p))*0.5f);
        while (j*(j-1)/2 > p) j--;
        while ((j+1)*j/2 <= p) j++;
        int i = p - j*(j-1)/2;
        int na = g_vlist[g*NB+i];
        int nb = g_vlist[g*NB+j];
        if (iou_suppress(g*NB+na, g*NB+nb))
            atomicOr(&g_mask[(g*NB+i)*MASKW + (j>>5)], 1u << (j&31));
    }
}

// ---------------- kernel 4: serial greedy (one warp per group) ----------------
__global__ void k_greedy()
{
    int g    = blockIdx.x;
    int lane = threadIdx.x;              // 32 threads
    __shared__ unsigned sm[NB*MASKW];
    int v = g_vcnt[g];
    for (int w = lane; w < v*MASKW; w += 32) sm[w] = g_mask[g*NB*MASKW + w];
    __syncwarp();

    unsigned supw = 0u;                  // lane l<12 owns suppression word l
    for (int i=0;i<v;i++){
        unsigned cur = __shfl_sync(0xFFFFFFFFu, supw, i>>5);
        if (!((cur >> (i&31)) & 1u)){
            if (lane < MASKW) supw |= sm[i*MASKW + lane];
        }
    }
    for (int base=0; base<v; base+=32){
        int tp  = base + lane;
        int src = (tp < v) ? (tp>>5) : 0;
        unsigned wv = __shfl_sync(0xFFFFFFFFu, supw, src);
        if (tp < v && !((wv >> (tp&31)) & 1u)){
            int n = g_vlist[g*NB+tp];
            g_kept[g*NB+n] = g_scores[g*NB+n];
        }
    }
}

// ---------------- kernel 5: per-image top-100 + output ----------------
__global__ void k_topk(float* __restrict__ out, int out_size)
{
    int b = blockIdx.x;
    int t = threadIdx.x;                 // 512 threads
    __shared__ unsigned long long sk[4096];

    for (int f = t; f < 4096; f += 512){
        unsigned long long key;
        if (f < NFG*NB){
            float sc = g_kept[b*NFG*NB + f];
            unsigned ub = __float_as_uint(sc);
            ub = (ub & 0x80000000u) ? ~ub : (ub | 0x80000000u);
            key = (((unsigned long long)(~ub)) << 32) | (unsigned)f;
        } else key = 0xFFFFFFFFFFFFFFFFull;
        sk[f] = key;
    }
    __syncthreads();

    for (int k=2;k<=4096;k<<=1)
        for (int j=k>>1;j>0;j>>=1){
            for (int p=t;p<4096;p+=512){
                int ixj = p ^ j;
                if (ixj > p){
                    unsigned long long A = sk[p], Bv = sk[ixj];
                    if ((A > Bv) == ((p & k) == 0)){ sk[p] = Bv; sk[ixj] = A; }
                }
            }
            __syncthreads();
        }

    if (t < DET){
        unsigned long long key = sk[t];
        unsigned f  = (unsigned)(key & 0xFFFFFFFFull);
        unsigned ub = ~((unsigned)(key >> 32));
        unsigned bits = (ub & 0x80000000u) ? (ub ^ 0x80000000u) : ~ub;
        float sc  = __uint_as_float(bits);
        bool okd  = sc > 0.0f;

        float vals[6] = {0.f,0.f,0.f,0.f,0.f,0.f};
        float lab = 0.0f;
        if (okd){
            int bi = b*NFG*NB + (int)f;
            #pragma unroll
            for (int kk=0;kk<5;kk++) vals[kk] = g_boxes[bi*5+kk];
            vals[5] = sc;
            lab = (float)((int)f / NB + 1);
        }
        int base = b*DET*6 + t*6;
        #pragma unroll
        for (int kk=0;kk<6;kk++) if (base+kk < out_size) out[base+kk] = vals[kk];
        int li = NIMG*DET*6 + b*DET + t;
        if (li < out_size) out[li] = lab;
    }
}

// ---------------- launcher ----------------
extern "C" void kernel_launch(void* const* d_in, const int* in_sizes, int n_in,
                              void* d_out, int out_size)
{
    const float* logits = (const float*)d_in[0];   // (768, 11)
    const float* reg    = (const float*)d_in[1];   // (768, 55)
    const float* rr     = (const float*)d_in[2];   // (768, 5)

    k_decode<<<(MTOT+255)/256, 256>>>(logits, reg, rr);
    k_sort  <<<NGRP, 512>>>();
    k_pairs <<<NGRP*SUBB, 256>>>();
    k_greedy<<<NGRP, 32>>>();
    k_topk  <<<NIMG, 512>>>((float*)d_out, out_size);
}